// round 14
// baseline (speedup 1.0000x reference)
#include <cuda_runtime.h>
#include <cuda_fp16.h>
#include <math.h>
#include <stdint.h>

#define D_IN   1024
#define HDIM   1024
#define BMAX   64
#define TMAXQ  1000
#define NGATE  4096
#define TOTAL_MAX 47872
#define NBLK   128

// ---------------- device scratch ----------------
__device__ float g_gates[(size_t)TOTAL_MAX * NGATE];
__device__ __half g_data16[(size_t)TOTAL_MAX * D_IN];
__device__ __half g_wih16[(size_t)NGATE * D_IN];
__device__ __half g_h16[2][BMAX * HDIM];
__device__ float g_cS[BMAX * HDIM];
__device__ int   g_bs[TMAXQ];
__device__ int   g_off[TMAXQ + 1];
__device__ unsigned g_bar;

// ---------------- helpers ----------------
__device__ __forceinline__ uint32_t smem_u32(const void* p) {
    uint32_t a;
    asm("{ .reg .u64 t; cvta.to.shared.u64 t, %1; cvt.u32.u64 %0, t; }" : "=r"(a) : "l"(p));
    return a;
}
__device__ __forceinline__ void cp16(uint32_t dst, const void* src) {
    asm volatile("cp.async.cg.shared.global [%0], [%1], 16;" :: "r"(dst), "l"(src));
}
#define CP_COMMIT() asm volatile("cp.async.commit_group;" ::: "memory")
#define CP_WAIT2()  asm volatile("cp.async.wait_group 2;"  ::: "memory")
#define CP_WAIT1()  asm volatile("cp.async.wait_group 1;"  ::: "memory")
#define CP_WAIT0()  asm volatile("cp.async.wait_group 0;"  ::: "memory")

__device__ __forceinline__ void mma16816h(float& d0, float& d1, float& d2, float& d3,
                                          uint32_t a0, uint32_t a1, uint32_t a2, uint32_t a3,
                                          uint32_t b0, uint32_t b1) {
    asm volatile(
        "mma.sync.aligned.m16n8k16.row.col.f32.f16.f16.f32 "
        "{%0,%1,%2,%3}, {%4,%5,%6,%7}, {%8,%9}, {%0,%1,%2,%3};"
        : "+f"(d0), "+f"(d1), "+f"(d2), "+f"(d3)
        : "r"(a0), "r"(a1), "r"(a2), "r"(a3), "r"(b0), "r"(b1));
}
__device__ __forceinline__ void ldsm4(uint32_t& r0, uint32_t& r1, uint32_t& r2, uint32_t& r3,
                                      uint32_t addr) {
    asm volatile("ldmatrix.sync.aligned.m8n8.x4.shared.b16 {%0,%1,%2,%3}, [%4];"
                 : "=r"(r0), "=r"(r1), "=r"(r2), "=r"(r3) : "r"(addr));
}
__device__ __forceinline__ uint32_t pack_h(__half a, __half b) {
    return (uint32_t)__half_as_ushort(a) | ((uint32_t)__half_as_ushort(b) << 16);
}

// ---------------- prep ----------------
__global__ void prep_kernel(const void* __restrict__ bs_raw,
                            const float* __restrict__ h0,
                            const float* __restrict__ c0, int T) {
    __shared__ int sbs[TMAXQ];
    const int* p = (const int*)bs_raw;
    bool is64 = (p[1] == 0);
    int tid = threadIdx.x;
    for (int t = tid; t < T; t += blockDim.x) sbs[t] = is64 ? p[2 * t] : p[t];
    __syncthreads();
    if (tid == 0) {
        g_bar = 0u;
        int acc = 0;
        for (int t = 0; t < T; t++) { g_off[t] = acc; g_bs[t] = sbs[t]; acc += sbs[t]; }
        g_off[T] = acc;
    }
    for (int i = tid; i < BMAX * HDIM; i += blockDim.x) {
        g_h16[0][i] = __float2half(h0[i]);
        g_cS[i] = c0[i];
    }
}

// ---------------- fp32 -> fp16 convert ----------------
__global__ void tohalf_kernel(const float* __restrict__ src,
                              __half* __restrict__ dst, size_t n) {
    for (size_t i = (size_t)blockIdx.x * blockDim.x + threadIdx.x; i < n;
         i += (size_t)gridDim.x * blockDim.x)
        dst[i] = __float2half(src[i]);
}

// ---------------- input GEMM: pure fp16, K=1024 (16 stages), 3-buffer --------
#define GI_STR    144
#define GI_OFF_BIAS 0
#define GI_OFF_A  512
#define GI_STG    (128 * GI_STR)
#define GI_OFF_B  (GI_OFF_A + 3 * GI_STG)
#define GI_SMEM   (GI_OFF_B + 3 * GI_STG)

__global__ __launch_bounds__(256) void gemm_input_tc(
    const float* __restrict__ b_ih, const float* __restrict__ b_hh, int total) {
    extern __shared__ __align__(16) char sm[];
    float* sBias = (float*)(sm + GI_OFF_BIAS);
    uint32_t sb = smem_u32(sm);
    int tid = threadIdx.x, wid = tid >> 5, lane = tid & 31;
    int tq = lane & 3;
    int col0 = blockIdx.x * 128, row0 = blockIdx.y * 128;
    int wm = wid & 1, wn = wid >> 1;

    int qr = lane & 7, qq = lane >> 3;
    int a_row = qr + ((qq & 1) << 3), a_k = (qq >> 1) << 3;
    int b_row = qr + ((qq >> 1) << 3), b_k = (qq & 1) << 3;

    for (int i = tid; i < 128; i += 256) sBias[i] = b_ih[col0 + i] + b_hh[col0 + i];

    float acc[4][4][4];
#pragma unroll
    for (int mf = 0; mf < 4; mf++)
#pragma unroll
        for (int nf = 0; nf < 4; nf++)
#pragma unroll
            for (int q = 0; q < 4; q++) acc[mf][nf][q] = 0.f;

    auto do_stage = [&](int st) {
        int buf = st % 3;
        int k0 = st * 64;
#pragma unroll
        for (int r = 0; r < 4; r++) {
            int c = tid + r * 256;
            int m = c >> 3, kc = (c & 7) * 8;
            int row = row0 + m; if (row >= total) row = total - 1;
            cp16(sb + GI_OFF_A + buf * GI_STG + m * GI_STR + kc * 2,
                 g_data16 + (size_t)row * 1024 + k0 + kc);
        }
#pragma unroll
        for (int r = 0; r < 4; r++) {
            int c = tid + r * 256;
            int m = c >> 3, kc = (c & 7) * 8;
            cp16(sb + GI_OFF_B + buf * GI_STG + m * GI_STR + kc * 2,
                 g_wih16 + (size_t)(col0 + m) * 1024 + k0 + kc);
        }
        CP_COMMIT();
    };

    do_stage(0);
    do_stage(1);
    for (int st = 0; st < 16; ++st) {
        if (st + 2 < 16) do_stage(st + 2);
        int rem = 15 - st;
        if (rem >= 2) { CP_WAIT2(); } else if (rem == 1) { CP_WAIT1(); } else { CP_WAIT0(); }
        __syncthreads();
        int buf = st % 3;
        uint32_t pA = sb + GI_OFF_A + buf * GI_STG;
        uint32_t pB = sb + GI_OFF_B + buf * GI_STG;
#pragma unroll
        for (int kk = 0; kk < 64; kk += 16) {
            uint32_t aF[4][4], bF[4][2];
#pragma unroll
            for (int mf = 0; mf < 4; mf++)
                ldsm4(aF[mf][0], aF[mf][1], aF[mf][2], aF[mf][3],
                      pA + (wm * 64 + mf * 16 + a_row) * GI_STR + (kk + a_k) * 2);
#pragma unroll
            for (int h = 0; h < 2; h++) {
                uint32_t r0, r1, r2, r3;
                ldsm4(r0, r1, r2, r3,
                      pB + (wn * 32 + h * 16 + b_row) * GI_STR + (kk + b_k) * 2);
                bF[h * 2][0] = r0; bF[h * 2][1] = r1;
                bF[h * 2 + 1][0] = r2; bF[h * 2 + 1][1] = r3;
            }
#pragma unroll
            for (int mf = 0; mf < 4; mf++)
#pragma unroll
                for (int nf = 0; nf < 4; nf++)
                    mma16816h(acc[mf][nf][0], acc[mf][nf][1], acc[mf][nf][2], acc[mf][nf][3],
                              aF[mf][0], aF[mf][1], aF[mf][2], aF[mf][3],
                              bF[nf][0], bF[nf][1]);
        }
        __syncthreads();
    }

    int g = lane >> 2;
#pragma unroll
    for (int mf = 0; mf < 4; mf++) {
        int r0 = row0 + wm * 64 + mf * 16 + g;
#pragma unroll
        for (int nf = 0; nf < 4; nf++) {
            int cl = wn * 32 + nf * 8 + tq * 2;
            float bb0 = sBias[cl], bb1 = sBias[cl + 1];
            if (r0 < total) {
                float2 v = { acc[mf][nf][0] + bb0, acc[mf][nf][1] + bb1 };
                *(float2*)&g_gates[(size_t)r0 * NGATE + col0 + cl] = v;
            }
            if (r0 + 8 < total) {
                float2 v = { acc[mf][nf][2] + bb0, acc[mf][nf][3] + bb1 };
                *(float2*)&g_gates[(size_t)(r0 + 8) * NGATE + col0 + cl] = v;
            }
        }
    }
}

// ---------------- persistent recurrence: fp16, 2 x 512-k stages, full prefetch
#define RW_STR   2064                          // 1024 fp16 + 16B pad
#define R_OFF_A  (32 * RW_STR)                 // 66048
#define RA_STR   1040                          // 512 fp16 + 16B pad
#define R_ASTG   (64 * RA_STR)                 // 66560
#define R_OFF_GS (R_OFF_A + 2 * R_ASTG)        // 199168
#define R_OFF_SG (R_OFF_GS + 2 * 8192)         // 215552
#define R_SMEM   (R_OFF_SG + 8192)             // 223744

__global__ __launch_bounds__(256) void step_persistent(
    const float* __restrict__ W_hh, float* __restrict__ out,
    int T, int total, int writeTail) {
    extern __shared__ __align__(16) char sm[];
    uint32_t sb = smem_u32(sm);
    float* GsAll = (float*)(sm + R_OFF_GS);
    float* sG = (float*)(sm + R_OFF_SG);
    int tid = threadIdx.x, wid = tid >> 5, lane = tid & 31;
    int g = lane >> 2, tq = lane & 3;
    int j0 = blockIdx.x * 8;
    int mw = wid & 3, kteam = wid >> 2;

    int qr = lane & 7, qq = lane >> 3;
    int a_row = qr + ((qq & 1) << 3), a_k = (qq >> 1) << 3;
    int b_row = qr + ((qq >> 1) << 3), b_k = (qq & 1) << 3;

    // one-time: convert this block's W_hh cols (fp32 -> fp16)
    for (int idx = tid; idx < 8192; idx += 256) {
        int c = idx >> 8;
        int k = (idx & 255) * 4;
        int n = (c >> 3) * HDIM + j0 + (c & 7);
        float4 v = *(const float4*)&W_hh[(size_t)n * HDIM + k];
        char* ph = sm + c * RW_STR + k * 2;
        *(uint32_t*)ph = pack_h(__float2half(v.x), __float2half(v.y));
        *(uint32_t*)(ph + 4) = pack_h(__float2half(v.z), __float2half(v.w));
    }
    __syncthreads();

    for (int t = 0; t < T; t++) {
        int pr = t & 1;
        const __half* hcur = g_h16[pr];
        int Bt = g_bs[t], off = g_off[t];
        int Btr = (Bt + 15) & ~15;
        int bsNext = (t + 1 < T) ? g_bs[t + 1] : 0;

        // stage st (0..1): 64 rows x 512 k fp16 (own buffer, no reuse)
        auto stageA = [&](int st) {
            int k0 = st * 512;
#pragma unroll
            for (int r = 0; r < 16; r++) {
                int c = tid + r * 256;            // 0..4095
                int b = c >> 6, kc = (c & 63) * 8;
                if (b < Btr)
                    cp16(sb + R_OFF_A + st * R_ASTG + b * RA_STR + kc * 2,
                         hcur + b * 1024 + k0 + kc);
            }
            CP_COMMIT();
        };

        // prologue: issue EVERYTHING up front — (sG + stage 0), stage 1
        {
#pragma unroll
            for (int u = 0; u < 2; u++) {
                int id = tid * 2 + u;
                int b = id >> 3, gi = (id >> 1) & 3, half = id & 1;
                int bc = (b < Bt) ? b : (Bt - 1);
                cp16(sb + R_OFF_SG + (uint32_t)(b * 32 + gi * 8 + half * 4) * 4,
                     &g_gates[(size_t)(off + bc) * NGATE + gi * HDIM + j0 + half * 4]);
            }
            stageA(0);      // group 0: SG + stage0
            stageA(1);      // group 1: stage1
        }

        bool wact = (mw * 16) < Bt;
        float acc[4][4];
#pragma unroll
        for (int nf = 0; nf < 4; nf++)
#pragma unroll
            for (int q = 0; q < 4; q++) acc[nf][q] = 0.f;

        for (int st = 0; st < 2; ++st) {
            if (st == 0) { CP_WAIT1(); } else { CP_WAIT0(); }
            __syncthreads();
            if (wact) {
                int k0w = st * 512;
                uint32_t pA = sb + R_OFF_A + st * R_ASTG + (mw * 16 + a_row) * RA_STR;
#pragma unroll
                for (int u = 0; u < 16; u++) {
                    int kk = kteam * 256 + u * 16;
                    uint32_t aF[4];
                    ldsm4(aF[0], aF[1], aF[2], aF[3], pA + (kk + a_k) * 2);
                    uint32_t bh[4][2];
#pragma unroll
                    for (int h = 0; h < 2; h++) {
                        uint32_t r0, r1, r2, r3;
                        uint32_t ab = sb + (h * 16 + b_row) * RW_STR + (k0w + kk + b_k) * 2;
                        ldsm4(r0, r1, r2, r3, ab);
                        bh[h * 2][0] = r0; bh[h * 2][1] = r1;
                        bh[h * 2 + 1][0] = r2; bh[h * 2 + 1][1] = r3;
                    }
#pragma unroll
                    for (int nf = 0; nf < 4; nf++)
                        mma16816h(acc[nf][0], acc[nf][1], acc[nf][2], acc[nf][3],
                                  aF[0], aF[1], aF[2], aF[3], bh[nf][0], bh[nf][1]);
                }
            }
        }

        if (wact) {
            float* Gs = GsAll + kteam * 2048;
            int b = mw * 16 + g;
#pragma unroll
            for (int nf = 0; nf < 4; nf++) {
                int c = nf * 8 + tq * 2;
                float2 v0 = { acc[nf][0], acc[nf][1] };
                float2 v1 = { acc[nf][2], acc[nf][3] };
                *(float2*)&Gs[b * 32 + c] = v0;
                *(float2*)&Gs[(b + 8) * 32 + c] = v1;
            }
        }
        __syncthreads();

        __half* hnext = g_h16[pr ^ 1];
        for (int it = tid; it < 512; it += 256) {
            int b = it >> 3, jl = it & 7;
            int j = j0 + jl;
            if (b < Bt) {
                int o0 = b * 32;
                float gi = GsAll[o0 + jl]      + GsAll[2048 + o0 + jl]      + sG[o0 + jl];
                float gf = GsAll[o0 + 8 + jl]  + GsAll[2048 + o0 + 8 + jl]  + sG[o0 + 8 + jl];
                float gg = GsAll[o0 + 16 + jl] + GsAll[2048 + o0 + 16 + jl] + sG[o0 + 16 + jl];
                float go = GsAll[o0 + 24 + jl] + GsAll[2048 + o0 + 24 + jl] + sG[o0 + 24 + jl];
                float i_ = 1.f / (1.f + __expf(-gi));
                float f_ = 1.f / (1.f + __expf(-gf));
                float g_ = tanhf(gg);
                float o_ = 1.f / (1.f + __expf(-go));
                float c_old = g_cS[b * HDIM + j];
                float c2 = f_ * c_old + i_ * g_;
                float h2 = o_ * tanhf(c2);
                g_cS[b * HDIM + j] = c2;
                hnext[b * HDIM + j] = __float2half(h2);
                out[(size_t)(off + b) * HDIM + j] = h2;
                if (writeTail && b >= bsNext) {
                    size_t hbase = (size_t)total * HDIM;
                    out[hbase + b * HDIM + j] = h2;
                    out[hbase + (size_t)BMAX * HDIM + b * HDIM + j] = c2;
                }
            } else {
                hnext[b * HDIM + j] = hcur[b * HDIM + j];
            }
        }

        // grid barrier
        __syncthreads();
        if (tid == 0) {
            asm volatile("red.release.gpu.add.u32 [%0], %1;" :: "l"(&g_bar), "r"(1u) : "memory");
            unsigned target = (unsigned)(t + 1) * (unsigned)NBLK;
            unsigned v;
            do {
                asm volatile("ld.acquire.gpu.u32 %0, [%1];" : "=r"(v) : "l"(&g_bar) : "memory");
            } while (v < target);
        }
        __syncthreads();
    }
}

// ---------------- launch ----------------
extern "C" void kernel_launch(void* const* d_in, const int* in_sizes, int n_in,
                              void* d_out, int out_size) {
    const float* data = (const float*)d_in[0];
    const void*  bs   = d_in[1];
    const float* W_ih = (const float*)d_in[2];
    const float* W_hh = (const float*)d_in[3];
    const float* b_ih = (const float*)d_in[4];
    const float* b_hh = (const float*)d_in[5];
    const float* h0   = (const float*)d_in[6];
    const float* c0   = (const float*)d_in[7];
    float* out = (float*)d_out;

    int total = in_sizes[0] / D_IN;
    int T = in_sizes[1];
    if (T > TMAXQ) T = T / 2;
    if (T > TMAXQ) T = TMAXQ;

    cudaFuncSetAttribute(gemm_input_tc, cudaFuncAttributeMaxDynamicSharedMemorySize, GI_SMEM);
    cudaFuncSetAttribute(step_persistent, cudaFuncAttributeMaxDynamicSharedMemorySize, R_SMEM);

    prep_kernel<<<1, 256>>>(bs, h0, c0, T);

    __half *d16, *w16;
    cudaGetSymbolAddress((void**)&d16, g_data16);
    cudaGetSymbolAddress((void**)&w16, g_wih16);
    tohalf_kernel<<<4096, 256>>>(data, d16, (size_t)total * D_IN);
    tohalf_kernel<<<2048, 256>>>(W_ih, w16, (size_t)NGATE * D_IN);

    dim3 grid(NGATE / 128, (total + 127) / 128);
    gemm_input_tc<<<grid, 256, GI_SMEM>>>(b_ih, b_hh, total);

    long long need = (long long)total * HDIM + 2LL * BMAX * HDIM;
    int writeTail = ((long long)out_size >= need) ? 1 : 0;
    step_persistent<<<NBLK, 256, R_SMEM>>>(W_hh, out, T, total, writeTail);
}

// round 15
// speedup vs baseline: 1.0129x; 1.0129x over previous
#include <cuda_runtime.h>
#include <cuda_fp16.h>
#include <math.h>
#include <stdint.h>

#define D_IN   1024
#define HDIM   1024
#define BMAX   64
#define TMAXQ  1000
#define NGATE  4096
#define TOTAL_MAX 47872
#define NBLK   128

// ---------------- device scratch ----------------
__device__ __half g_gates[(size_t)TOTAL_MAX * NGATE];   // fp16 gates (392 MB)
__device__ __half g_data16[(size_t)TOTAL_MAX * D_IN];
__device__ __half g_wih16[(size_t)NGATE * D_IN];
__device__ __half g_h16[2][BMAX * HDIM];
__device__ float g_cS[BMAX * HDIM];
__device__ int   g_bs[TMAXQ];
__device__ int   g_off[TMAXQ + 1];
__device__ unsigned g_bar;

// ---------------- helpers ----------------
__device__ __forceinline__ uint32_t smem_u32(const void* p) {
    uint32_t a;
    asm("{ .reg .u64 t; cvta.to.shared.u64 t, %1; cvt.u32.u64 %0, t; }" : "=r"(a) : "l"(p));
    return a;
}
__device__ __forceinline__ void cp16(uint32_t dst, const void* src) {
    asm volatile("cp.async.cg.shared.global [%0], [%1], 16;" :: "r"(dst), "l"(src));
}
#define CP_COMMIT() asm volatile("cp.async.commit_group;" ::: "memory")
#define CP_WAIT2()  asm volatile("cp.async.wait_group 2;"  ::: "memory")
#define CP_WAIT1()  asm volatile("cp.async.wait_group 1;"  ::: "memory")
#define CP_WAIT0()  asm volatile("cp.async.wait_group 0;"  ::: "memory")

__device__ __forceinline__ void mma16816h(float& d0, float& d1, float& d2, float& d3,
                                          uint32_t a0, uint32_t a1, uint32_t a2, uint32_t a3,
                                          uint32_t b0, uint32_t b1) {
    asm volatile(
        "mma.sync.aligned.m16n8k16.row.col.f32.f16.f16.f32 "
        "{%0,%1,%2,%3}, {%4,%5,%6,%7}, {%8,%9}, {%0,%1,%2,%3};"
        : "+f"(d0), "+f"(d1), "+f"(d2), "+f"(d3)
        : "r"(a0), "r"(a1), "r"(a2), "r"(a3), "r"(b0), "r"(b1));
}
__device__ __forceinline__ void ldsm4(uint32_t& r0, uint32_t& r1, uint32_t& r2, uint32_t& r3,
                                      uint32_t addr) {
    asm volatile("ldmatrix.sync.aligned.m8n8.x4.shared.b16 {%0,%1,%2,%3}, [%4];"
                 : "=r"(r0), "=r"(r1), "=r"(r2), "=r"(r3) : "r"(addr));
}
__device__ __forceinline__ uint32_t pack_h(__half a, __half b) {
    return (uint32_t)__half_as_ushort(a) | ((uint32_t)__half_as_ushort(b) << 16);
}

// ---------------- prep ----------------
__global__ void prep_kernel(const void* __restrict__ bs_raw,
                            const float* __restrict__ h0,
                            const float* __restrict__ c0, int T) {
    __shared__ int sbs[TMAXQ];
    const int* p = (const int*)bs_raw;
    bool is64 = (p[1] == 0);
    int tid = threadIdx.x;
    for (int t = tid; t < T; t += blockDim.x) sbs[t] = is64 ? p[2 * t] : p[t];
    __syncthreads();
    if (tid == 0) {
        g_bar = 0u;
        int acc = 0;
        for (int t = 0; t < T; t++) { g_off[t] = acc; g_bs[t] = sbs[t]; acc += sbs[t]; }
        g_off[T] = acc;
    }
    for (int i = tid; i < BMAX * HDIM; i += blockDim.x) {
        g_h16[0][i] = __float2half(h0[i]);
        g_cS[i] = c0[i];
    }
}

// ---------------- fp32 -> fp16 convert ----------------
__global__ void tohalf_kernel(const float* __restrict__ src,
                              __half* __restrict__ dst, size_t n) {
    for (size_t i = (size_t)blockIdx.x * blockDim.x + threadIdx.x; i < n;
         i += (size_t)gridDim.x * blockDim.x)
        dst[i] = __float2half(src[i]);
}

// ---------------- input GEMM: pure fp16, K=1024 (16 stages), 3-buffer --------
#define GI_STR    144
#define GI_OFF_BIAS 0
#define GI_OFF_A  512
#define GI_STG    (128 * GI_STR)
#define GI_OFF_B  (GI_OFF_A + 3 * GI_STG)
#define GI_SMEM   (GI_OFF_B + 3 * GI_STG)

__global__ __launch_bounds__(256) void gemm_input_tc(
    const float* __restrict__ b_ih, const float* __restrict__ b_hh, int total) {
    extern __shared__ __align__(16) char sm[];
    float* sBias = (float*)(sm + GI_OFF_BIAS);
    uint32_t sb = smem_u32(sm);
    int tid = threadIdx.x, wid = tid >> 5, lane = tid & 31;
    int tq = lane & 3;
    int col0 = blockIdx.x * 128, row0 = blockIdx.y * 128;
    int wm = wid & 1, wn = wid >> 1;

    int qr = lane & 7, qq = lane >> 3;
    int a_row = qr + ((qq & 1) << 3), a_k = (qq >> 1) << 3;
    int b_row = qr + ((qq >> 1) << 3), b_k = (qq & 1) << 3;

    for (int i = tid; i < 128; i += 256) sBias[i] = b_ih[col0 + i] + b_hh[col0 + i];

    float acc[4][4][4];
#pragma unroll
    for (int mf = 0; mf < 4; mf++)
#pragma unroll
        for (int nf = 0; nf < 4; nf++)
#pragma unroll
            for (int q = 0; q < 4; q++) acc[mf][nf][q] = 0.f;

    auto do_stage = [&](int st) {
        int buf = st % 3;
        int k0 = st * 64;
#pragma unroll
        for (int r = 0; r < 4; r++) {
            int c = tid + r * 256;
            int m = c >> 3, kc = (c & 7) * 8;
            int row = row0 + m; if (row >= total) row = total - 1;
            cp16(sb + GI_OFF_A + buf * GI_STG + m * GI_STR + kc * 2,
                 g_data16 + (size_t)row * 1024 + k0 + kc);
        }
#pragma unroll
        for (int r = 0; r < 4; r++) {
            int c = tid + r * 256;
            int m = c >> 3, kc = (c & 7) * 8;
            cp16(sb + GI_OFF_B + buf * GI_STG + m * GI_STR + kc * 2,
                 g_wih16 + (size_t)(col0 + m) * 1024 + k0 + kc);
        }
        CP_COMMIT();
    };

    do_stage(0);
    do_stage(1);
    for (int st = 0; st < 16; ++st) {
        if (st + 2 < 16) do_stage(st + 2);
        int rem = 15 - st;
        if (rem >= 2) { CP_WAIT2(); } else if (rem == 1) { CP_WAIT1(); } else { CP_WAIT0(); }
        __syncthreads();
        int buf = st % 3;
        uint32_t pA = sb + GI_OFF_A + buf * GI_STG;
        uint32_t pB = sb + GI_OFF_B + buf * GI_STG;
#pragma unroll
        for (int kk = 0; kk < 64; kk += 16) {
            uint32_t aF[4][4], bF[4][2];
#pragma unroll
            for (int mf = 0; mf < 4; mf++)
                ldsm4(aF[mf][0], aF[mf][1], aF[mf][2], aF[mf][3],
                      pA + (wm * 64 + mf * 16 + a_row) * GI_STR + (kk + a_k) * 2);
#pragma unroll
            for (int h = 0; h < 2; h++) {
                uint32_t r0, r1, r2, r3;
                ldsm4(r0, r1, r2, r3,
                      pB + (wn * 32 + h * 16 + b_row) * GI_STR + (kk + b_k) * 2);
                bF[h * 2][0] = r0; bF[h * 2][1] = r1;
                bF[h * 2 + 1][0] = r2; bF[h * 2 + 1][1] = r3;
            }
#pragma unroll
            for (int mf = 0; mf < 4; mf++)
#pragma unroll
                for (int nf = 0; nf < 4; nf++)
                    mma16816h(acc[mf][nf][0], acc[mf][nf][1], acc[mf][nf][2], acc[mf][nf][3],
                              aF[mf][0], aF[mf][1], aF[mf][2], aF[mf][3],
                              bF[nf][0], bF[nf][1]);
        }
        __syncthreads();
    }

    int g = lane >> 2;
#pragma unroll
    for (int mf = 0; mf < 4; mf++) {
        int r0 = row0 + wm * 64 + mf * 16 + g;
#pragma unroll
        for (int nf = 0; nf < 4; nf++) {
            int cl = wn * 32 + nf * 8 + tq * 2;
            float bb0 = sBias[cl], bb1 = sBias[cl + 1];
            if (r0 < total) {
                __half2 v = __floats2half2_rn(acc[mf][nf][0] + bb0, acc[mf][nf][1] + bb1);
                *(__half2*)&g_gates[(size_t)r0 * NGATE + col0 + cl] = v;
            }
            if (r0 + 8 < total) {
                __half2 v = __floats2half2_rn(acc[mf][nf][2] + bb0, acc[mf][nf][3] + bb1);
                *(__half2*)&g_gates[(size_t)(r0 + 8) * NGATE + col0 + cl] = v;
            }
        }
    }
}

// ---------------- persistent recurrence: fp16, 4 x 256-k stages, depth-2 -----
#define RW_STR   2064                          // 1024 fp16 + 16B pad
#define R_OFF_A  (32 * RW_STR)                 // 66048
#define RA_STR   528                           // 256 fp16 + 16B pad
#define R_ASTG   (64 * RA_STR)                 // 33792
#define R_OFF_GS (R_OFF_A + 3 * R_ASTG)        // 167424
#define R_OFF_SG (R_OFF_GS + 2 * 8192)         // 183808
#define R_SMEM   (R_OFF_SG + 4096)             // 187904

__global__ __launch_bounds__(256) void step_persistent(
    const float* __restrict__ W_hh, float* __restrict__ out,
    int T, int total, int writeTail) {
    extern __shared__ __align__(16) char sm[];
    uint32_t sb = smem_u32(sm);
    float* GsAll = (float*)(sm + R_OFF_GS);
    __half* sG = (__half*)(sm + R_OFF_SG);
    int tid = threadIdx.x, wid = tid >> 5, lane = tid & 31;
    int g = lane >> 2, tq = lane & 3;
    int j0 = blockIdx.x * 8;
    int mw = wid & 3, kteam = wid >> 2;

    int qr = lane & 7, qq = lane >> 3;
    int a_row = qr + ((qq & 1) << 3), a_k = (qq >> 1) << 3;
    int b_row = qr + ((qq >> 1) << 3), b_k = (qq & 1) << 3;

    // one-time: convert this block's W_hh cols (fp32 -> fp16)
    for (int idx = tid; idx < 8192; idx += 256) {
        int c = idx >> 8;
        int k = (idx & 255) * 4;
        int n = (c >> 3) * HDIM + j0 + (c & 7);
        float4 v = *(const float4*)&W_hh[(size_t)n * HDIM + k];
        char* ph = sm + c * RW_STR + k * 2;
        *(uint32_t*)ph = pack_h(__float2half(v.x), __float2half(v.y));
        *(uint32_t*)(ph + 4) = pack_h(__float2half(v.z), __float2half(v.w));
    }
    __syncthreads();

    for (int t = 0; t < T; t++) {
        int pr = t & 1;
        const __half* hcur = g_h16[pr];
        int Bt = g_bs[t], off = g_off[t];
        int Btr = (Bt + 15) & ~15;
        int bsNext = (t + 1 < T) ? g_bs[t + 1] : 0;

        // stage st (0..3): 64 rows x 256 k fp16, 3 rotating buffers
        auto stageA = [&](int st) {
            int buf = st % 3;
            int k0 = st * 256;
#pragma unroll
            for (int r = 0; r < 8; r++) {
                int c = tid + r * 256;            // 0..2047
                int b = c >> 5, kc = (c & 31) * 8;
                if (b < Btr)
                    cp16(sb + R_OFF_A + buf * R_ASTG + b * RA_STR + kc * 2,
                         hcur + b * 1024 + k0 + kc);
            }
            CP_COMMIT();
        };

        // prologue: (sG fp16 + stage 0) as one group, then stage 1 (depth-2)
        {
            // sG: 64 b x 32 gate-cols x 2B = 4096 B = 256 chunks of 16B
            int b = tid >> 2, gi = tid & 3;
            int bc = (b < Bt) ? b : (Bt - 1);
            cp16(sb + R_OFF_SG + (uint32_t)(b * 32 + gi * 8) * 2,
                 &g_gates[(size_t)(off + bc) * NGATE + gi * HDIM + j0]);
            stageA(0);      // group: SG + stage0
            stageA(1);
        }

        bool wact = (mw * 16) < Bt;
        float acc[4][4];
#pragma unroll
        for (int nf = 0; nf < 4; nf++)
#pragma unroll
            for (int q = 0; q < 4; q++) acc[nf][q] = 0.f;

        for (int st = 0; st < 4; ++st) {
            if (st + 2 < 4) stageA(st + 2);
            int rem = 3 - st;
            if (rem >= 2) { CP_WAIT2(); } else if (rem == 1) { CP_WAIT1(); } else { CP_WAIT0(); }
            __syncthreads();
            if (wact) {
                int buf = st % 3;
                int k0w = st * 256;
                uint32_t pA = sb + R_OFF_A + buf * R_ASTG + (mw * 16 + a_row) * RA_STR;
#pragma unroll
                for (int u = 0; u < 8; u++) {
                    int kk = kteam * 128 + u * 16;
                    uint32_t aF[4];
                    ldsm4(aF[0], aF[1], aF[2], aF[3], pA + (kk + a_k) * 2);
                    uint32_t bh[4][2];
#pragma unroll
                    for (int h = 0; h < 2; h++) {
                        uint32_t r0, r1, r2, r3;
                        uint32_t ab = sb + (h * 16 + b_row) * RW_STR + (k0w + kk + b_k) * 2;
                        ldsm4(r0, r1, r2, r3, ab);
                        bh[h * 2][0] = r0; bh[h * 2][1] = r1;
                        bh[h * 2 + 1][0] = r2; bh[h * 2 + 1][1] = r3;
                    }
#pragma unroll
                    for (int nf = 0; nf < 4; nf++)
                        mma16816h(acc[nf][0], acc[nf][1], acc[nf][2], acc[nf][3],
                                  aF[0], aF[1], aF[2], aF[3], bh[nf][0], bh[nf][1]);
                }
            }
            __syncthreads();
        }

        if (wact) {
            float* Gs = GsAll + kteam * 2048;
            int b = mw * 16 + g;
#pragma unroll
            for (int nf = 0; nf < 4; nf++) {
                int c = nf * 8 + tq * 2;
                float2 v0 = { acc[nf][0], acc[nf][1] };
                float2 v1 = { acc[nf][2], acc[nf][3] };
                *(float2*)&Gs[b * 32 + c] = v0;
                *(float2*)&Gs[(b + 8) * 32 + c] = v1;
            }
        }
        __syncthreads();

        __half* hnext = g_h16[pr ^ 1];
        for (int it = tid; it < 512; it += 256) {
            int b = it >> 3, jl = it & 7;
            int j = j0 + jl;
            if (b < Bt) {
                int o0 = b * 32;
                float gi = GsAll[o0 + jl]      + GsAll[2048 + o0 + jl]      + __half2float(sG[o0 + jl]);
                float gf = GsAll[o0 + 8 + jl]  + GsAll[2048 + o0 + 8 + jl]  + __half2float(sG[o0 + 8 + jl]);
                float gg = GsAll[o0 + 16 + jl] + GsAll[2048 + o0 + 16 + jl] + __half2float(sG[o0 + 16 + jl]);
                float go = GsAll[o0 + 24 + jl] + GsAll[2048 + o0 + 24 + jl] + __half2float(sG[o0 + 24 + jl]);
                float i_ = 1.f / (1.f + __expf(-gi));
                float f_ = 1.f / (1.f + __expf(-gf));
                float g_ = tanhf(gg);
                float o_ = 1.f / (1.f + __expf(-go));
                float c_old = g_cS[b * HDIM + j];
                float c2 = f_ * c_old + i_ * g_;
                float h2 = o_ * tanhf(c2);
                g_cS[b * HDIM + j] = c2;
                hnext[b * HDIM + j] = __float2half(h2);
                out[(size_t)(off + b) * HDIM + j] = h2;
                if (writeTail && b >= bsNext) {
                    size_t hbase = (size_t)total * HDIM;
                    out[hbase + b * HDIM + j] = h2;
                    out[hbase + (size_t)BMAX * HDIM + b * HDIM + j] = c2;
                }
            } else {
                hnext[b * HDIM + j] = hcur[b * HDIM + j];
            }
        }

        // grid barrier
        __syncthreads();
        if (tid == 0) {
            asm volatile("red.release.gpu.add.u32 [%0], %1;" :: "l"(&g_bar), "r"(1u) : "memory");
            unsigned target = (unsigned)(t + 1) * (unsigned)NBLK;
            unsigned v;
            do {
                asm volatile("ld.acquire.gpu.u32 %0, [%1];" : "=r"(v) : "l"(&g_bar) : "memory");
            } while (v < target);
        }
        __syncthreads();
    }
}

// ---------------- launch ----------------
extern "C" void kernel_launch(void* const* d_in, const int* in_sizes, int n_in,
                              void* d_out, int out_size) {
    const float* data = (const float*)d_in[0];
    const void*  bs   = d_in[1];
    const float* W_ih = (const float*)d_in[2];
    const float* W_hh = (const float*)d_in[3];
    const float* b_ih = (const float*)d_in[4];
    const float* b_hh = (const float*)d_in[5];
    const float* h0   = (const float*)d_in[6];
    const float* c0   = (const float*)d_in[7];
    float* out = (float*)d_out;

    int total = in_sizes[0] / D_IN;
    int T = in_sizes[1];
    if (T > TMAXQ) T = T / 2;
    if (T > TMAXQ) T = TMAXQ;

    cudaFuncSetAttribute(gemm_input_tc, cudaFuncAttributeMaxDynamicSharedMemorySize, GI_SMEM);
    cudaFuncSetAttribute(step_persistent, cudaFuncAttributeMaxDynamicSharedMemorySize, R_SMEM);

    prep_kernel<<<1, 256>>>(bs, h0, c0, T);

    __half *d16, *w16;
    cudaGetSymbolAddress((void**)&d16, g_data16);
    cudaGetSymbolAddress((void**)&w16, g_wih16);
    tohalf_kernel<<<4096, 256>>>(data, d16, (size_t)total * D_IN);
    tohalf_kernel<<<2048, 256>>>(W_ih, w16, (size_t)NGATE * D_IN);

    dim3 grid(NGATE / 128, (total + 127) / 128);
    gemm_input_tc<<<grid, 256, GI_SMEM>>>(b_ih, b_hh, total);

    long long need = (long long)total * HDIM + 2LL * BMAX * HDIM;
    int writeTail = ((long long)out_size >= need) ? 1 : 0;
    step_persistent<<<NBLK, 256, R_SMEM>>>(W_hh, out, T, total, writeTail);
}

// round 16
// speedup vs baseline: 1.0845x; 1.0707x over previous
#include <cuda_runtime.h>
#include <cuda_fp16.h>
#include <math.h>
#include <stdint.h>

#define D_IN   1024
#define HDIM   1024
#define BMAX   64
#define TMAXQ  1000
#define NGATE  4096
#define TOTAL_MAX 47872
#define NBLK   128

// ---------------- device scratch ----------------
__device__ __half g_gates[(size_t)TOTAL_MAX * NGATE];   // fp16 gates (392 MB)
__device__ __half g_data16[(size_t)TOTAL_MAX * D_IN];
__device__ __half g_wih16[(size_t)NGATE * D_IN];
__device__ __half g_h16[2][BMAX * HDIM];
__device__ int   g_bs[TMAXQ];
__device__ int   g_off[TMAXQ + 1];
__device__ unsigned g_bar;

// ---------------- helpers ----------------
__device__ __forceinline__ uint32_t smem_u32(const void* p) {
    uint32_t a;
    asm("{ .reg .u64 t; cvta.to.shared.u64 t, %1; cvt.u32.u64 %0, t; }" : "=r"(a) : "l"(p));
    return a;
}
__device__ __forceinline__ void cp16(uint32_t dst, const void* src) {
    asm volatile("cp.async.cg.shared.global [%0], [%1], 16;" :: "r"(dst), "l"(src));
}
#define CP_COMMIT() asm volatile("cp.async.commit_group;" ::: "memory")
#define CP_WAIT2()  asm volatile("cp.async.wait_group 2;"  ::: "memory")
#define CP_WAIT1()  asm volatile("cp.async.wait_group 1;"  ::: "memory")
#define CP_WAIT0()  asm volatile("cp.async.wait_group 0;"  ::: "memory")

__device__ __forceinline__ void mma16816h(float& d0, float& d1, float& d2, float& d3,
                                          uint32_t a0, uint32_t a1, uint32_t a2, uint32_t a3,
                                          uint32_t b0, uint32_t b1) {
    asm volatile(
        "mma.sync.aligned.m16n8k16.row.col.f32.f16.f16.f32 "
        "{%0,%1,%2,%3}, {%4,%5,%6,%7}, {%8,%9}, {%0,%1,%2,%3};"
        : "+f"(d0), "+f"(d1), "+f"(d2), "+f"(d3)
        : "r"(a0), "r"(a1), "r"(a2), "r"(a3), "r"(b0), "r"(b1));
}
__device__ __forceinline__ void ldsm4(uint32_t& r0, uint32_t& r1, uint32_t& r2, uint32_t& r3,
                                      uint32_t addr) {
    asm volatile("ldmatrix.sync.aligned.m8n8.x4.shared.b16 {%0,%1,%2,%3}, [%4];"
                 : "=r"(r0), "=r"(r1), "=r"(r2), "=r"(r3) : "r"(addr));
}
__device__ __forceinline__ uint32_t pack_h(__half a, __half b) {
    return (uint32_t)__half_as_ushort(a) | ((uint32_t)__half_as_ushort(b) << 16);
}
__device__ __forceinline__ float fast_sigmoid(float x) {
    return __fdividef(1.f, 1.f + __expf(-x));
}
__device__ __forceinline__ float fast_tanh(float x) {
    return __fdividef(2.f, 1.f + __expf(-2.f * x)) - 1.f;
}
__device__ __forceinline__ void stcs(float* p, float v) {
    asm volatile("st.global.cs.f32 [%0], %1;" :: "l"(p), "f"(v));
}

// ---------------- prep ----------------
__global__ void prep_kernel(const void* __restrict__ bs_raw,
                            const float* __restrict__ h0, int T) {
    __shared__ int sbs[TMAXQ];
    const int* p = (const int*)bs_raw;
    bool is64 = (p[1] == 0);
    int tid = threadIdx.x;
    for (int t = tid; t < T; t += blockDim.x) sbs[t] = is64 ? p[2 * t] : p[t];
    __syncthreads();
    if (tid == 0) {
        g_bar = 0u;
        int acc = 0;
        for (int t = 0; t < T; t++) { g_off[t] = acc; g_bs[t] = sbs[t]; acc += sbs[t]; }
        g_off[T] = acc;
    }
    for (int i = tid; i < BMAX * HDIM; i += blockDim.x)
        g_h16[0][i] = __float2half(h0[i]);
}

// ---------------- fp32 -> fp16 convert ----------------
__global__ void tohalf_kernel(const float* __restrict__ src,
                              __half* __restrict__ dst, size_t n) {
    for (size_t i = (size_t)blockIdx.x * blockDim.x + threadIdx.x; i < n;
         i += (size_t)gridDim.x * blockDim.x)
        dst[i] = __float2half(src[i]);
}

// ---------------- input GEMM: pure fp16, K=1024 (16 stages), 3-buffer --------
#define GI_STR    144
#define GI_OFF_BIAS 0
#define GI_OFF_A  512
#define GI_STG    (128 * GI_STR)
#define GI_OFF_B  (GI_OFF_A + 3 * GI_STG)
#define GI_SMEM   (GI_OFF_B + 3 * GI_STG)

__global__ __launch_bounds__(256) void gemm_input_tc(
    const float* __restrict__ b_ih, const float* __restrict__ b_hh, int total) {
    extern __shared__ __align__(16) char sm[];
    float* sBias = (float*)(sm + GI_OFF_BIAS);
    uint32_t sb = smem_u32(sm);
    int tid = threadIdx.x, wid = tid >> 5, lane = tid & 31;
    int tq = lane & 3;
    int col0 = blockIdx.x * 128, row0 = blockIdx.y * 128;
    int wm = wid & 1, wn = wid >> 1;

    int qr = lane & 7, qq = lane >> 3;
    int a_row = qr + ((qq & 1) << 3), a_k = (qq >> 1) << 3;
    int b_row = qr + ((qq >> 1) << 3), b_k = (qq & 1) << 3;

    for (int i = tid; i < 128; i += 256) sBias[i] = b_ih[col0 + i] + b_hh[col0 + i];

    float acc[4][4][4];
#pragma unroll
    for (int mf = 0; mf < 4; mf++)
#pragma unroll
        for (int nf = 0; nf < 4; nf++)
#pragma unroll
            for (int q = 0; q < 4; q++) acc[mf][nf][q] = 0.f;

    auto do_stage = [&](int st) {
        int buf = st % 3;
        int k0 = st * 64;
#pragma unroll
        for (int r = 0; r < 4; r++) {
            int c = tid + r * 256;
            int m = c >> 3, kc = (c & 7) * 8;
            int row = row0 + m; if (row >= total) row = total - 1;
            cp16(sb + GI_OFF_A + buf * GI_STG + m * GI_STR + kc * 2,
                 g_data16 + (size_t)row * 1024 + k0 + kc);
        }
#pragma unroll
        for (int r = 0; r < 4; r++) {
            int c = tid + r * 256;
            int m = c >> 3, kc = (c & 7) * 8;
            cp16(sb + GI_OFF_B + buf * GI_STG + m * GI_STR + kc * 2,
                 g_wih16 + (size_t)(col0 + m) * 1024 + k0 + kc);
        }
        CP_COMMIT();
    };

    do_stage(0);
    do_stage(1);
    for (int st = 0; st < 16; ++st) {
        if (st + 2 < 16) do_stage(st + 2);
        int rem = 15 - st;
        if (rem >= 2) { CP_WAIT2(); } else if (rem == 1) { CP_WAIT1(); } else { CP_WAIT0(); }
        __syncthreads();
        int buf = st % 3;
        uint32_t pA = sb + GI_OFF_A + buf * GI_STG;
        uint32_t pB = sb + GI_OFF_B + buf * GI_STG;
#pragma unroll
        for (int kk = 0; kk < 64; kk += 16) {
            uint32_t aF[4][4], bF[4][2];
#pragma unroll
            for (int mf = 0; mf < 4; mf++)
                ldsm4(aF[mf][0], aF[mf][1], aF[mf][2], aF[mf][3],
                      pA + (wm * 64 + mf * 16 + a_row) * GI_STR + (kk + a_k) * 2);
#pragma unroll
            for (int h = 0; h < 2; h++) {
                uint32_t r0, r1, r2, r3;
                ldsm4(r0, r1, r2, r3,
                      pB + (wn * 32 + h * 16 + b_row) * GI_STR + (kk + b_k) * 2);
                bF[h * 2][0] = r0; bF[h * 2][1] = r1;
                bF[h * 2 + 1][0] = r2; bF[h * 2 + 1][1] = r3;
            }
#pragma unroll
            for (int mf = 0; mf < 4; mf++)
#pragma unroll
                for (int nf = 0; nf < 4; nf++)
                    mma16816h(acc[mf][nf][0], acc[mf][nf][1], acc[mf][nf][2], acc[mf][nf][3],
                              aF[mf][0], aF[mf][1], aF[mf][2], aF[mf][3],
                              bF[nf][0], bF[nf][1]);
        }
        __syncthreads();
    }

    int g = lane >> 2;
#pragma unroll
    for (int mf = 0; mf < 4; mf++) {
        int r0 = row0 + wm * 64 + mf * 16 + g;
#pragma unroll
        for (int nf = 0; nf < 4; nf++) {
            int cl = wn * 32 + nf * 8 + tq * 2;
            float bb0 = sBias[cl], bb1 = sBias[cl + 1];
            if (r0 < total) {
                __half2 v = __floats2half2_rn(acc[mf][nf][0] + bb0, acc[mf][nf][1] + bb1);
                *(__half2*)&g_gates[(size_t)r0 * NGATE + col0 + cl] = v;
            }
            if (r0 + 8 < total) {
                __half2 v = __floats2half2_rn(acc[mf][nf][2] + bb0, acc[mf][nf][3] + bb1);
                *(__half2*)&g_gates[(size_t)(r0 + 8) * NGATE + col0 + cl] = v;
            }
        }
    }
}

// ---------------- persistent recurrence: fp16, 4 x 256-k stages, depth-2 -----
// smem c state; fast transcendentals; streaming out stores.
#define RW_STR   2064                          // 1024 fp16 + 16B pad
#define R_OFF_A  (32 * RW_STR)                 // 66048
#define RA_STR   528                           // 256 fp16 + 16B pad
#define R_ASTG   (64 * RA_STR)                 // 33792
#define R_OFF_GS (R_OFF_A + 3 * R_ASTG)        // 167424
#define R_OFF_SG (R_OFF_GS + 2 * 8192)         // 183808
#define R_OFF_SC (R_OFF_SG + 4096)             // 187904
#define R_SMEM   (R_OFF_SC + 2048)             // 189952

__global__ __launch_bounds__(256) void step_persistent(
    const float* __restrict__ W_hh, const float* __restrict__ c0,
    float* __restrict__ out, int T, int total, int writeTail) {
    extern __shared__ __align__(16) char sm[];
    uint32_t sb = smem_u32(sm);
    float* GsAll = (float*)(sm + R_OFF_GS);
    __half* sG = (__half*)(sm + R_OFF_SG);
    float* sC = (float*)(sm + R_OFF_SC);       // [b*8 + jl], block-private c state
    int tid = threadIdx.x, wid = tid >> 5, lane = tid & 31;
    int g = lane >> 2, tq = lane & 3;
    int j0 = blockIdx.x * 8;
    int mw = wid & 3, kteam = wid >> 2;

    int qr = lane & 7, qq = lane >> 3;
    int a_row = qr + ((qq & 1) << 3), a_k = (qq >> 1) << 3;
    int b_row = qr + ((qq >> 1) << 3), b_k = (qq & 1) << 3;

    // one-time: convert this block's W_hh cols (fp32 -> fp16)
    for (int idx = tid; idx < 8192; idx += 256) {
        int c = idx >> 8;
        int k = (idx & 255) * 4;
        int n = (c >> 3) * HDIM + j0 + (c & 7);
        float4 v = *(const float4*)&W_hh[(size_t)n * HDIM + k];
        char* ph = sm + c * RW_STR + k * 2;
        *(uint32_t*)ph = pack_h(__float2half(v.x), __float2half(v.y));
        *(uint32_t*)(ph + 4) = pack_h(__float2half(v.z), __float2half(v.w));
    }
    // one-time: c state into smem (block-private columns)
    for (int it = tid; it < 512; it += 256) {
        int b = it >> 3, jl = it & 7;
        sC[it] = c0[b * HDIM + j0 + jl];
    }
    __syncthreads();

    for (int t = 0; t < T; t++) {
        int pr = t & 1;
        const __half* hcur = g_h16[pr];
        int Bt = g_bs[t], off = g_off[t];
        int Btr = (Bt + 15) & ~15;
        int bsNext = (t + 1 < T) ? g_bs[t + 1] : 0;

        // stage st (0..3): 64 rows x 256 k fp16, 3 rotating buffers
        auto stageA = [&](int st) {
            int buf = st % 3;
            int k0 = st * 256;
#pragma unroll
            for (int r = 0; r < 8; r++) {
                int c = tid + r * 256;            // 0..2047
                int b = c >> 5, kc = (c & 31) * 8;
                if (b < Btr)
                    cp16(sb + R_OFF_A + buf * R_ASTG + b * RA_STR + kc * 2,
                         hcur + b * 1024 + k0 + kc);
            }
            CP_COMMIT();
        };

        // prologue: (sG fp16 + stage 0) as one group, then stage 1 (depth-2)
        {
            int b = tid >> 2, gi = tid & 3;
            int bc = (b < Bt) ? b : (Bt - 1);
            cp16(sb + R_OFF_SG + (uint32_t)(b * 32 + gi * 8) * 2,
                 &g_gates[(size_t)(off + bc) * NGATE + gi * HDIM + j0]);
            stageA(0);      // group: SG + stage0
            stageA(1);
        }

        bool wact = (mw * 16) < Bt;
        float acc[4][4];
#pragma unroll
        for (int nf = 0; nf < 4; nf++)
#pragma unroll
            for (int q = 0; q < 4; q++) acc[nf][q] = 0.f;

        for (int st = 0; st < 4; ++st) {
            if (st + 2 < 4) stageA(st + 2);
            int rem = 3 - st;
            if (rem >= 2) { CP_WAIT2(); } else if (rem == 1) { CP_WAIT1(); } else { CP_WAIT0(); }
            __syncthreads();
            if (wact) {
                int buf = st % 3;
                int k0w = st * 256;
                uint32_t pA = sb + R_OFF_A + buf * R_ASTG + (mw * 16 + a_row) * RA_STR;
#pragma unroll
                for (int u = 0; u < 8; u++) {
                    int kk = kteam * 128 + u * 16;
                    uint32_t aF[4];
                    ldsm4(aF[0], aF[1], aF[2], aF[3], pA + (kk + a_k) * 2);
                    uint32_t bh[4][2];
#pragma unroll
                    for (int h = 0; h < 2; h++) {
                        uint32_t r0, r1, r2, r3;
                        uint32_t ab = sb + (h * 16 + b_row) * RW_STR + (k0w + kk + b_k) * 2;
                        ldsm4(r0, r1, r2, r3, ab);
                        bh[h * 2][0] = r0; bh[h * 2][1] = r1;
                        bh[h * 2 + 1][0] = r2; bh[h * 2 + 1][1] = r3;
                    }
#pragma unroll
                    for (int nf = 0; nf < 4; nf++)
                        mma16816h(acc[nf][0], acc[nf][1], acc[nf][2], acc[nf][3],
                                  aF[0], aF[1], aF[2], aF[3], bh[nf][0], bh[nf][1]);
                }
            }
            if (st < 3) __syncthreads();   // final stage: Gs writes are warp-private
        }

        if (wact) {
            float* Gs = GsAll + kteam * 2048;
            int b = mw * 16 + g;
#pragma unroll
            for (int nf = 0; nf < 4; nf++) {
                int c = nf * 8 + tq * 2;
                float2 v0 = { acc[nf][0], acc[nf][1] };
                float2 v1 = { acc[nf][2], acc[nf][3] };
                *(float2*)&Gs[b * 32 + c] = v0;
                *(float2*)&Gs[(b + 8) * 32 + c] = v1;
            }
        }
        __syncthreads();

        __half* hnext = g_h16[pr ^ 1];
        for (int it = tid; it < 512; it += 256) {
            int b = it >> 3, jl = it & 7;
            int j = j0 + jl;
            if (b < Bt) {
                int o0 = b * 32;
                float gi = GsAll[o0 + jl]      + GsAll[2048 + o0 + jl]      + __half2float(sG[o0 + jl]);
                float gf = GsAll[o0 + 8 + jl]  + GsAll[2048 + o0 + 8 + jl]  + __half2float(sG[o0 + 8 + jl]);
                float gg = GsAll[o0 + 16 + jl] + GsAll[2048 + o0 + 16 + jl] + __half2float(sG[o0 + 16 + jl]);
                float go = GsAll[o0 + 24 + jl] + GsAll[2048 + o0 + 24 + jl] + __half2float(sG[o0 + 24 + jl]);
                float i_ = fast_sigmoid(gi);
                float f_ = fast_sigmoid(gf);
                float g_ = fast_tanh(gg);
                float o_ = fast_sigmoid(go);
                float c_old = sC[it];
                float c2 = f_ * c_old + i_ * g_;
                float h2 = o_ * fast_tanh(c2);
                sC[it] = c2;
                hnext[b * HDIM + j] = __float2half(h2);
                stcs(&out[(size_t)(off + b) * HDIM + j], h2);
                if (writeTail && b >= bsNext) {
                    size_t hbase = (size_t)total * HDIM;
                    stcs(&out[hbase + b * HDIM + j], h2);
                    stcs(&out[hbase + (size_t)BMAX * HDIM + b * HDIM + j], c2);
                }
            } else {
                hnext[b * HDIM + j] = hcur[b * HDIM + j];
            }
        }

        // grid barrier
        __syncthreads();
        if (tid == 0) {
            asm volatile("red.release.gpu.add.u32 [%0], %1;" :: "l"(&g_bar), "r"(1u) : "memory");
            unsigned target = (unsigned)(t + 1) * (unsigned)NBLK;
            unsigned v;
            do {
                asm volatile("ld.acquire.gpu.u32 %0, [%1];" : "=r"(v) : "l"(&g_bar) : "memory");
            } while (v < target);
        }
        __syncthreads();
    }
}

// ---------------- launch ----------------
extern "C" void kernel_launch(void* const* d_in, const int* in_sizes, int n_in,
                              void* d_out, int out_size) {
    const float* data = (const float*)d_in[0];
    const void*  bs   = d_in[1];
    const float* W_ih = (const float*)d_in[2];
    const float* W_hh = (const float*)d_in[3];
    const float* b_ih = (const float*)d_in[4];
    const float* b_hh = (const float*)d_in[5];
    const float* h0   = (const float*)d_in[6];
    const float* c0   = (const float*)d_in[7];
    float* out = (float*)d_out;

    int total = in_sizes[0] / D_IN;
    int T = in_sizes[1];
    if (T > TMAXQ) T = T / 2;
    if (T > TMAXQ) T = TMAXQ;

    cudaFuncSetAttribute(gemm_input_tc, cudaFuncAttributeMaxDynamicSharedMemorySize, GI_SMEM);
    cudaFuncSetAttribute(step_persistent, cudaFuncAttributeMaxDynamicSharedMemorySize, R_SMEM);

    prep_kernel<<<1, 256>>>(bs, h0, T);

    __half *d16, *w16;
    cudaGetSymbolAddress((void**)&d16, g_data16);
    cudaGetSymbolAddress((void**)&w16, g_wih16);
    tohalf_kernel<<<4096, 256>>>(data, d16, (size_t)total * D_IN);
    tohalf_kernel<<<2048, 256>>>(W_ih, w16, (size_t)NGATE * D_IN);

    dim3 grid(NGATE / 128, (total + 127) / 128);
    gemm_input_tc<<<grid, 256, GI_SMEM>>>(b_ih, b_hh, total);

    long long need = (long long)total * HDIM + 2LL * BMAX * HDIM;
    int writeTail = ((long long)out_size >= need) ? 1 : 0;
    step_persistent<<<NBLK, 256, R_SMEM>>>(W_hh, c0, out, T, total, writeTail);
}